// round 15
// baseline (speedup 1.0000x reference)
#include <cuda_runtime.h>

// ---------------- Problem constants ----------------
#define BATCH    512
#define FEAT     1024
#define O1       2000
#define O2       1000
#define NLUT     64
#define NCLS     10
#define TAU      3.3333333f

#define RG       8
#define NG       (BATCH / RG)       // 64

// producer slices: 4 per 8-row group -> 256 producer tasks
#define A_OSPL   4
#define A_OUT    (O1 / A_OSPL)      // 500
#define NPROD    (NG * A_OSPL)      // 256

// consumer tasks: 10 per group -> 640 (== grid size; CTAs 0..255 dual-role)
#define B_OSPL   10
#define B_OUT    (O2 / B_OSPL)      // 100 = 1 class
#define NPAIR    (B_OUT / 2)        // 50
#define L2PS     66                 // padded u64 stride per LUT pair
#define BTHREADS 448
#define GRID     (NG * B_OSPL)      // 640

#define SMEM_BYTES 32000            // max(producer 27392, consumer 32000)

// ---------------- Device scratch ----------------
__device__ float g_h1[NG * O1 * RG];      // 4 MB, layout [g][o][r]
__device__ int   g_flag[NG];              // producers done per group
__device__ int   g_done[NG];              // consumers done per group (reset)

// ---------------- f32x2 helpers ----------------
__device__ __forceinline__ unsigned long long pk2(float lo, float hi) {
    unsigned long long r;
    asm("mov.b64 %0, {%1, %2};" : "=l"(r) : "f"(lo), "f"(hi));
    return r;
}
__device__ __forceinline__ void upk2(float& lo, float& hi, unsigned long long v) {
    asm("mov.b64 {%0, %1}, %2;" : "=f"(lo), "=f"(hi) : "l"(v));
}
__device__ __forceinline__ unsigned long long fma2(unsigned long long a,
                                                   unsigned long long b,
                                                   unsigned long long c) {
    unsigned long long d;
    asm("fma.rn.f32x2 %0, %1, %2, %3;" : "=l"(d) : "l"(a), "l"(b), "l"(c));
    return d;
}
__device__ __forceinline__ unsigned long long lerp2(unsigned long long a,
                                                    unsigned long long b,
                                                    unsigned long long x,
                                                    unsigned long long nx) {
    return fma2(x, b, fma2(nx, a, a));
}

// ================== Fused dual-role kernel ==================
__global__ __launch_bounds__(BTHREADS, 4)
void dwn_fused(const float* __restrict__ x,     const float* __restrict__ thr,
               const float* __restrict__ luts1, const int* __restrict__ idx1,
               const float* __restrict__ luts2, const int* __restrict__ idx2,
               float* __restrict__ out)
{
    extern __shared__ char smem[];
    const int bid = blockIdx.x;
    const int tid = threadIdx.x;

    // ============ ROLE 1 (bids 0..255): produce slice bid ============
    if (bid < NPROD) {
        float*    s_thr  = (float*)smem;                        // 3072 f
        unsigned* s_bits = (unsigned*)(s_thr + FEAT * 3);       // 8*97 u32
        int*      s_idx1 = (int*)(s_bits + RG * 97);            // 3000 i

        const int g     = bid >> 2;
        const int os    = bid & 3;
        const int obase = os * A_OUT;
        const int lane  = tid & 31;

        for (int i = tid; i < FEAT * 3 / 4; i += BTHREADS)
            ((float4*)s_thr)[i] = __ldg((const float4*)thr + i);
        for (int i = tid; i < A_OUT * 6; i += BTHREADS)
            s_idx1[i] = __ldg(idx1 + obase * 6 + i);
        __syncthreads();

        // thermometer (warp windows row-aligned: 448 and 1024 both /32)
        for (int i = tid; i < RG * FEAT; i += BTHREADS) {
            const int r = i >> 10;
            const int f = i & 1023;
            float xv = __ldg(x + (g * RG + r) * FEAT + f);
            float t0 = s_thr[f * 3 + 0];
            float t1 = s_thr[f * 3 + 1];
            float t2 = s_thr[f * 3 + 2];
            unsigned b0 = __ballot_sync(0xFFFFFFFFu, xv > t0);
            unsigned b1 = __ballot_sync(0xFFFFFFFFu, xv > t1);
            unsigned b2 = __ballot_sync(0xFFFFFFFFu, xv > t2);
            if (lane == 0) {
                unsigned* wp = s_bits + r * 97 + (f >> 5);
                wp[0]  = b0;
                wp[32] = b1;
                wp[64] = b2;
            }
        }
        __syncthreads();

        #pragma unroll 2
        for (int t = tid; t < A_OUT * RG; t += BTHREADS) {
            const int ol = t >> 3;
            const int r  = t & 7;
            const unsigned* bp = s_bits + r * 97;
            int code = 0;
            #pragma unroll
            for (int k = 0; k < 6; k++) {
                unsigned i  = (unsigned)s_idx1[ol * 6 + k];
                unsigned f  = i / 3u;
                unsigned tt = i - f * 3u;
                unsigned wv = bp[tt * 32 + (f >> 5)];
                code = (code << 1) | (int)((wv >> (f & 31)) & 1u);
            }
            g_h1[(g * O1 + obase + ol) * RG + r] =
                __ldg(luts1 + (obase + ol) * NLUT + code);
        }

        __syncthreads();
        __threadfence();
        if (tid == 0) atomicAdd(&g_flag[g], 1);
        __syncthreads();   // smem handoff: producer layout -> consumer layout
    }

    // ============ ROLE 2 (all 640 CTAs): consume task bid ============
    {
        unsigned long long* s_l2p = (unsigned long long*)smem;     // 50*66 u64
        int*                s_idx = (int*)(s_l2p + NPAIR * L2PS);  // 600 i
        float*              s_h2  = (float*)(s_idx + B_OUT * 6);   // 800 f

        const int g     = bid / B_OSPL;
        const int os    = bid % B_OSPL;
        const int obase = os * B_OUT;

        // stage luts2 + idx2 (consumers-only overlap this with producers)
        for (int i = tid; i < NPAIR * (NLUT / 4); i += BTHREADS) {
            const int p = i >> 4, q = i & 15;
            float4 a = __ldg((const float4*)(luts2 + (obase + p) * NLUT) + q);
            float4 b = __ldg((const float4*)(luts2 + (obase + NPAIR + p) * NLUT) + q);
            unsigned long long* d = s_l2p + p * L2PS + q * 4;
            d[0] = pk2(a.x, b.x);
            d[1] = pk2(a.y - a.x, b.y - b.x);
            d[2] = pk2(a.z, b.z);
            d[3] = pk2(a.w - a.z, b.w - b.z);
        }
        for (int i = tid; i < B_OUT * 6; i += BTHREADS)
            s_idx[i] = __ldg(idx2 + obase * 6 + i);
        __syncthreads();

        // wait for this group's 4 producers
        if (tid == 0) {
            volatile int* fl = g_flag + g;
            while (*fl < A_OSPL) __nanosleep(64);
            __threadfence();
        }
        __syncthreads();

        if (tid < RG * NPAIR) {                  // 400 compute threads
            const int p = tid >> 3;
            const int r = tid & 7;
            const unsigned long long* Lp = s_l2p + p * L2PS;
            const float* h1g = g_h1 + (size_t)g * O1 * RG + r;
            const int* ipA = s_idx + p * 6;
            const int* ipB = s_idx + (p + NPAIR) * 6;

            unsigned long long xp5, xp4, xn4, xp3, xn3, xp2, xn2;
            {
                float a, b;
                a = __ldg(h1g + ipA[5] * RG); b = __ldg(h1g + ipB[5] * RG);
                xp5 = pk2(a, b);
                a = __ldg(h1g + ipA[4] * RG); b = __ldg(h1g + ipB[4] * RG);
                xp4 = pk2(a, b); xn4 = pk2(-a, -b);
                a = __ldg(h1g + ipA[3] * RG); b = __ldg(h1g + ipB[3] * RG);
                xp3 = pk2(a, b); xn3 = pk2(-a, -b);
                a = __ldg(h1g + ipA[2] * RG); b = __ldg(h1g + ipB[2] * RG);
                xp2 = pk2(a, b); xn2 = pk2(-a, -b);
            }

            unsigned long long u[4];
            #pragma unroll
            for (int t = 0; t < 4; t++) {
                const unsigned long long* Lt = Lp + 16 * t;
                ulonglong2 cc;
                unsigned long long w0, w1, v0, v1, h0, h1v;
                cc = *(const ulonglong2*)(Lt + 0);  w0 = fma2(xp5, cc.y, cc.x);
                cc = *(const ulonglong2*)(Lt + 2);  w1 = fma2(xp5, cc.y, cc.x);
                v0 = lerp2(w0, w1, xp4, xn4);
                cc = *(const ulonglong2*)(Lt + 4);  w0 = fma2(xp5, cc.y, cc.x);
                cc = *(const ulonglong2*)(Lt + 6);  w1 = fma2(xp5, cc.y, cc.x);
                v1 = lerp2(w0, w1, xp4, xn4);
                h0 = lerp2(v0, v1, xp3, xn3);
                cc = *(const ulonglong2*)(Lt + 8);  w0 = fma2(xp5, cc.y, cc.x);
                cc = *(const ulonglong2*)(Lt + 10); w1 = fma2(xp5, cc.y, cc.x);
                v0 = lerp2(w0, w1, xp4, xn4);
                cc = *(const ulonglong2*)(Lt + 12); w0 = fma2(xp5, cc.y, cc.x);
                cc = *(const ulonglong2*)(Lt + 14); w1 = fma2(xp5, cc.y, cc.x);
                v1 = lerp2(w0, w1, xp4, xn4);
                h1v = lerp2(v0, v1, xp3, xn3);
                u[t] = lerp2(h0, h1v, xp2, xn2);
            }
            float a1, b1;
            a1 = __ldg(h1g + ipA[1] * RG); b1 = __ldg(h1g + ipB[1] * RG);
            unsigned long long xp1 = pk2(a1, b1), xn1 = pk2(-a1, -b1);
            unsigned long long t0 = lerp2(u[0], u[1], xp1, xn1);
            unsigned long long t1 = lerp2(u[2], u[3], xp1, xn1);
            a1 = __ldg(h1g + ipA[0] * RG); b1 = __ldg(h1g + ipB[0] * RG);
            unsigned long long xp0 = pk2(a1, b1), xn0 = pk2(-a1, -b1);
            unsigned long long res = lerp2(t0, t1, xp0, xn0);

            float hA, hB;
            upk2(hA, hB, res);
            s_h2[p * RG + r]           = hA;
            s_h2[(p + NPAIR) * RG + r] = hB;
        }
        __syncthreads();

        // deterministic fixed-order class sum
        if (tid < RG) {
            const float* hp = s_h2 + tid;
            float s0 = 0.f, s1 = 0.f;
            #pragma unroll 4
            for (int j = 0; j < B_OUT; j += 2) {
                s0 += hp[(j + 0) * RG];
                s1 += hp[(j + 1) * RG];
            }
            out[(g * RG + tid) * NCLS + os] = (s0 + s1) / TAU;
        }

        // reset flags for next graph replay (last consumer of group g)
        if (tid == 0) {
            int old = atomicAdd(&g_done[g], 1);
            if (old == B_OSPL - 1) {
                g_flag[g] = 0;
                g_done[g] = 0;
                __threadfence();
            }
        }
    }
}

// ================== launch ==================
extern "C" void kernel_launch(void* const* d_in, const int* in_sizes, int n_in,
                              void* d_out, int out_size)
{
    const float* x      = (const float*)d_in[0];
    const float* thr    = (const float*)d_in[1];
    const float* luts1  = (const float*)d_in[2];
    const int*   idx1   = (const int*)  d_in[3];
    const float* luts2  = (const float*)d_in[4];
    const int*   idx2   = (const int*)  d_in[5];
    float*       out    = (float*)d_out;

    dwn_fused<<<GRID, BTHREADS, SMEM_BYTES>>>(x, thr, luts1, idx1,
                                              luts2, idx2, out);
}

// round 16
// speedup vs baseline: 1.1400x; 1.1400x over previous
#include <cuda_runtime.h>

// ---------------- Problem constants ----------------
#define BATCH    512
#define FEAT     1024
#define O1       2000
#define O2       1000
#define NLUT     64
#define NCLS     10
#define TAU      3.3333333f

#define RG       8
#define NG       (BATCH / RG)       // 64

// kA: 4 output slices -> 256 CTAs, 512 threads (measured-best shape)
#define A_OSPL   4
#define A_OUT    (O1 / A_OSPL)      // 500

// kB (R10/R13 config, reproduced 12.5-13.1us): 640 CTAs, 4 CTAs/SM
#define B_OSPL   10
#define B_OUT    (O2 / B_OSPL)      // 100 = 1 class
#define NPAIR    (B_OUT / 2)        // 50
#define L2PS     66                 // padded u64 stride per LUT pair
#define BTHREADS 448

// ---------------- Device scratch ----------------
__device__ float g_h1[NG * O1 * RG];      // 4 MB, layout [g][o][r]

// ---------------- f32x2 helpers ----------------
__device__ __forceinline__ unsigned long long pk2(float lo, float hi) {
    unsigned long long r;
    asm("mov.b64 %0, {%1, %2};" : "=l"(r) : "f"(lo), "f"(hi));
    return r;
}
__device__ __forceinline__ void upk2(float& lo, float& hi, unsigned long long v) {
    asm("mov.b64 {%0, %1}, %2;" : "=f"(lo), "=f"(hi) : "l"(v));
}
__device__ __forceinline__ unsigned long long fma2(unsigned long long a,
                                                   unsigned long long b,
                                                   unsigned long long c) {
    unsigned long long d;
    asm("fma.rn.f32x2 %0, %1, %2, %3;" : "=l"(d) : "l"(a), "l"(b), "l"(c));
    return d;
}
__device__ __forceinline__ unsigned long long lerp2(unsigned long long a,
                                                    unsigned long long b,
                                                    unsigned long long x,
                                                    unsigned long long nx) {
    return fma2(x, b, fma2(nx, a, a));
}

// ============ Kernel 1: thermometer (byte bits, NO ballots) + gather ============
// 256 CTAs, 512 threads. Bits stored as bytes s_bits[bitidx*8 + r]:
// thermo loop has no cross-lane coupling -> unroll-4 gives real MLP;
// gather needs no div-by-3 or shifts, 8 lanes read 8 consecutive bytes.
__global__ __launch_bounds__(512)
void k01_layer1(const float* __restrict__ x,     const float* __restrict__ thr,
                const float* __restrict__ luts1, const int* __restrict__ idx1)
{
    __shared__ float         s_thr[FEAT * 3];        // 12 KB
    __shared__ unsigned char s_bits[FEAT * 3 * RG];  // 24 KB, [bit][r]
    __shared__ int           s_idx[A_OUT * 6];       // 12 KB

    const int g     = blockIdx.x >> 2;
    const int os    = blockIdx.x & 3;
    const int obase = os * A_OUT;
    const int tid   = threadIdx.x;

    for (int i = tid; i < FEAT * 3 / 4; i += 512)
        ((float4*)s_thr)[i] = __ldg((const float4*)thr + i);
    for (int i = tid; i < A_OUT * 6; i += 512)
        s_idx[i] = __ldg(idx1 + obase * 6 + i);
    __syncthreads();

    // thermometer: 16 iters/thread, independent chains -> unroll 4
    #pragma unroll 4
    for (int i = tid; i < RG * FEAT; i += 512) {
        const int r = i >> 10;
        const int f = i & 1023;
        float xv = __ldg(x + (g * RG + r) * FEAT + f);
        unsigned char* bp = s_bits + (f * 3) * RG + r;
        bp[0 * RG] = (unsigned char)(xv > s_thr[f * 3 + 0]);
        bp[1 * RG] = (unsigned char)(xv > s_thr[f * 3 + 1]);
        bp[2 * RG] = (unsigned char)(xv > s_thr[f * 3 + 2]);
    }
    __syncthreads();

    // gather: task t -> (o = t>>3, r = t&7); byte reads, no bit math
    #pragma unroll 2
    for (int t = tid; t < A_OUT * RG; t += 512) {
        const int ol = t >> 3;
        const int r  = t & 7;
        const int* ip = s_idx + ol * 6;
        int code = 0;
        #pragma unroll
        for (int k = 0; k < 6; k++) {
            code = (code << 1) | (int)s_bits[ip[k] * RG + r];
        }
        g_h1[(g * O1 + obase + ol) * RG + r] =
            __ldg(luts1 + (obase + ol) * NLUT + code);
    }
}

// ============ Kernel 2: layer 2 interp + one class sum per CTA ============
// Exact R10/R13 configuration — unchanged (3x reproduced at 12.5-13.1us).
__global__ __launch_bounds__(BTHREADS, 4)
void kB_layer2(const float* __restrict__ luts2, const int* __restrict__ idx2,
               float* __restrict__ out)
{
    extern __shared__ char smem[];
    unsigned long long* s_l2p = (unsigned long long*)smem;        // 50*66 u64
    int*                s_idx = (int*)(s_l2p + NPAIR * L2PS);     // 600 i
    float*              s_h2  = (float*)(s_idx + B_OUT * 6);      // 800 f

    const int g     = blockIdx.x / B_OSPL;
    const int os    = blockIdx.x % B_OSPL;
    const int obase = os * B_OUT;
    const int tid   = threadIdx.x;

    for (int i = tid; i < NPAIR * (NLUT / 4); i += BTHREADS) {
        const int p = i >> 4, q = i & 15;
        float4 a = __ldg((const float4*)(luts2 + (obase + p) * NLUT) + q);
        float4 b = __ldg((const float4*)(luts2 + (obase + NPAIR + p) * NLUT) + q);
        unsigned long long* d = s_l2p + p * L2PS + q * 4;
        d[0] = pk2(a.x, b.x);
        d[1] = pk2(a.y - a.x, b.y - b.x);
        d[2] = pk2(a.z, b.z);
        d[3] = pk2(a.w - a.z, b.w - b.z);
    }
    for (int i = tid; i < B_OUT * 6; i += BTHREADS)
        s_idx[i] = __ldg(idx2 + obase * 6 + i);
    __syncthreads();

    if (tid < RG * NPAIR) {                  // 400 compute threads
        const int p = tid >> 3;
        const int r = tid & 7;
        const unsigned long long* Lp = s_l2p + p * L2PS;
        const float* h1g = g_h1 + (size_t)g * O1 * RG + r;
        const int* ipA = s_idx + p * 6;
        const int* ipB = s_idx + (p + NPAIR) * 6;

        unsigned long long xp5, xp4, xn4, xp3, xn3, xp2, xn2;
        {
            float a, b;
            a = __ldg(h1g + ipA[5] * RG); b = __ldg(h1g + ipB[5] * RG);
            xp5 = pk2(a, b);
            a = __ldg(h1g + ipA[4] * RG); b = __ldg(h1g + ipB[4] * RG);
            xp4 = pk2(a, b); xn4 = pk2(-a, -b);
            a = __ldg(h1g + ipA[3] * RG); b = __ldg(h1g + ipB[3] * RG);
            xp3 = pk2(a, b); xn3 = pk2(-a, -b);
            a = __ldg(h1g + ipA[2] * RG); b = __ldg(h1g + ipB[2] * RG);
            xp2 = pk2(a, b); xn2 = pk2(-a, -b);
        }

        unsigned long long u[4];
        #pragma unroll
        for (int t = 0; t < 4; t++) {
            const unsigned long long* Lt = Lp + 16 * t;
            ulonglong2 c;
            unsigned long long w0, w1, v0, v1, h0, h1v;
            c = *(const ulonglong2*)(Lt + 0);  w0 = fma2(xp5, c.y, c.x);
            c = *(const ulonglong2*)(Lt + 2);  w1 = fma2(xp5, c.y, c.x);
            v0 = lerp2(w0, w1, xp4, xn4);
            c = *(const ulonglong2*)(Lt + 4);  w0 = fma2(xp5, c.y, c.x);
            c = *(const ulonglong2*)(Lt + 6);  w1 = fma2(xp5, c.y, c.x);
            v1 = lerp2(w0, w1, xp4, xn4);
            h0 = lerp2(v0, v1, xp3, xn3);
            c = *(const ulonglong2*)(Lt + 8);  w0 = fma2(xp5, c.y, c.x);
            c = *(const ulonglong2*)(Lt + 10); w1 = fma2(xp5, c.y, c.x);
            v0 = lerp2(w0, w1, xp4, xn4);
            c = *(const ulonglong2*)(Lt + 12); w0 = fma2(xp5, c.y, c.x);
            c = *(const ulonglong2*)(Lt + 14); w1 = fma2(xp5, c.y, c.x);
            v1 = lerp2(w0, w1, xp4, xn4);
            h1v = lerp2(v0, v1, xp3, xn3);
            u[t] = lerp2(h0, h1v, xp2, xn2);
        }
        float a1, b1;
        a1 = __ldg(h1g + ipA[1] * RG); b1 = __ldg(h1g + ipB[1] * RG);
        unsigned long long xp1 = pk2(a1, b1), xn1 = pk2(-a1, -b1);
        unsigned long long t0 = lerp2(u[0], u[1], xp1, xn1);
        unsigned long long t1 = lerp2(u[2], u[3], xp1, xn1);
        a1 = __ldg(h1g + ipA[0] * RG); b1 = __ldg(h1g + ipB[0] * RG);
        unsigned long long xp0 = pk2(a1, b1), xn0 = pk2(-a1, -b1);
        unsigned long long res = lerp2(t0, t1, xp0, xn0);

        float hA, hB;
        upk2(hA, hB, res);
        s_h2[p * RG + r]           = hA;
        s_h2[(p + NPAIR) * RG + r] = hB;
    }
    __syncthreads();

    if (tid < RG) {
        const float* hp = s_h2 + tid;
        float s0 = 0.f, s1 = 0.f;
        #pragma unroll 4
        for (int j = 0; j < B_OUT; j += 2) {
            s0 += hp[(j + 0) * RG];
            s1 += hp[(j + 1) * RG];
        }
        out[(g * RG + tid) * NCLS + os] = (s0 + s1) / TAU;
    }
}

// ================== launch ==================
extern "C" void kernel_launch(void* const* d_in, const int* in_sizes, int n_in,
                              void* d_out, int out_size)
{
    const float* x      = (const float*)d_in[0];
    const float* thr    = (const float*)d_in[1];
    const float* luts1  = (const float*)d_in[2];
    const int*   idx1   = (const int*)  d_in[3];
    const float* luts2  = (const float*)d_in[4];
    const int*   idx2   = (const int*)  d_in[5];
    float*       out    = (float*)d_out;

    const int smemB = NPAIR * L2PS * 8 + B_OUT * 6 * 4 + B_OUT * RG * 4;
    static bool attr_set = false;
    if (!attr_set) {
        cudaFuncSetAttribute(kB_layer2, cudaFuncAttributeMaxDynamicSharedMemorySize, smemB);
        attr_set = true;
    }

    k01_layer1<<<NG * A_OSPL, 512>>>(x, thr, luts1, idx1);
    kB_layer2<<<NG * B_OSPL, BTHREADS, smemB>>>(luts2, idx2, out);
}

// round 17
// speedup vs baseline: 1.1738x; 1.0297x over previous
#include <cuda_runtime.h>

// ---------------- Problem constants ----------------
#define BATCH    512
#define FEAT     1024
#define O1       2000
#define O2       1000
#define NLUT     64
#define NCLS     10
#define TAU      3.3333333f

#define RG       8
#define NG       (BATCH / RG)       // 64

// kA: 4 output slices -> 256 CTAs, 512 threads (R16 measured-best)
#define A_OSPL   4
#define A_OUT    (O1 / A_OSPL)      // 500

// kB: 640 CTAs; 512 threads x 4 CTAs/SM = 2048 thr = 64 warps/SM (was 56)
#define B_OSPL   10
#define B_OUT    (O2 / B_OSPL)      // 100 = 1 class
#define NPAIR    (B_OUT / 2)        // 50
#define L2PS     66                 // padded u64 stride per LUT pair
#define BTHREADS 512

// ---------------- Device scratch ----------------
__device__ float g_h1[NG * O1 * RG];      // 4 MB, layout [g][o][r]

// ---------------- f32x2 helpers ----------------
__device__ __forceinline__ unsigned long long pk2(float lo, float hi) {
    unsigned long long r;
    asm("mov.b64 %0, {%1, %2};" : "=l"(r) : "f"(lo), "f"(hi));
    return r;
}
__device__ __forceinline__ void upk2(float& lo, float& hi, unsigned long long v) {
    asm("mov.b64 {%0, %1}, %2;" : "=f"(lo), "=f"(hi) : "l"(v));
}
__device__ __forceinline__ unsigned long long fma2(unsigned long long a,
                                                   unsigned long long b,
                                                   unsigned long long c) {
    unsigned long long d;
    asm("fma.rn.f32x2 %0, %1, %2, %3;" : "=l"(d) : "l"(a), "l"(b), "l"(c));
    return d;
}
__device__ __forceinline__ unsigned long long lerp2(unsigned long long a,
                                                    unsigned long long b,
                                                    unsigned long long x,
                                                    unsigned long long nx) {
    return fma2(x, b, fma2(nx, a, a));
}

// ============ Kernel 1: thermometer (byte bits) + layer-1 gather ============
// Exact R16 winner — unchanged.
__global__ __launch_bounds__(512)
void k01_layer1(const float* __restrict__ x,     const float* __restrict__ thr,
                const float* __restrict__ luts1, const int* __restrict__ idx1)
{
    __shared__ float         s_thr[FEAT * 3];        // 12 KB
    __shared__ unsigned char s_bits[FEAT * 3 * RG];  // 24 KB, [bit][r]
    __shared__ int           s_idx[A_OUT * 6];       // 12 KB

    const int g     = blockIdx.x >> 2;
    const int os    = blockIdx.x & 3;
    const int obase = os * A_OUT;
    const int tid   = threadIdx.x;

    for (int i = tid; i < FEAT * 3 / 4; i += 512)
        ((float4*)s_thr)[i] = __ldg((const float4*)thr + i);
    for (int i = tid; i < A_OUT * 6; i += 512)
        s_idx[i] = __ldg(idx1 + obase * 6 + i);
    __syncthreads();

    // thermometer: independent chains -> unroll 4 (R16 win)
    #pragma unroll 4
    for (int i = tid; i < RG * FEAT; i += 512) {
        const int r = i >> 10;
        const int f = i & 1023;
        float xv = __ldg(x + (g * RG + r) * FEAT + f);
        unsigned char* bp = s_bits + (f * 3) * RG + r;
        bp[0 * RG] = (unsigned char)(xv > s_thr[f * 3 + 0]);
        bp[1 * RG] = (unsigned char)(xv > s_thr[f * 3 + 1]);
        bp[2 * RG] = (unsigned char)(xv > s_thr[f * 3 + 2]);
    }
    __syncthreads();

    // gather: byte reads, no bit math
    #pragma unroll 2
    for (int t = tid; t < A_OUT * RG; t += 512) {
        const int ol = t >> 3;
        const int r  = t & 7;
        const int* ip = s_idx + ol * 6;
        int code = 0;
        #pragma unroll
        for (int k = 0; k < 6; k++) {
            code = (code << 1) | (int)s_bits[ip[k] * RG + r];
        }
        g_h1[(g * O1 + obase + ol) * RG + r] =
            __ldg(luts1 + (obase + ol) * NLUT + code);
    }
}

// ============ Kernel 2: layer 2 interp + one class sum per CTA ============
// R10/R13 math unchanged; block 512 (was 448) -> 64 warps/SM at 4 CTAs/SM.
__global__ __launch_bounds__(BTHREADS, 4)
void kB_layer2(const float* __restrict__ luts2, const int* __restrict__ idx2,
               float* __restrict__ out)
{
    extern __shared__ char smem[];
    unsigned long long* s_l2p = (unsigned long long*)smem;        // 50*66 u64
    int*                s_idx = (int*)(s_l2p + NPAIR * L2PS);     // 600 i
    float*              s_h2  = (float*)(s_idx + B_OUT * 6);      // 800 f

    const int g     = blockIdx.x / B_OSPL;
    const int os    = blockIdx.x % B_OSPL;
    const int obase = os * B_OUT;
    const int tid   = threadIdx.x;

    for (int i = tid; i < NPAIR * (NLUT / 4); i += BTHREADS) {
        const int p = i >> 4, q = i & 15;
        float4 a = __ldg((const float4*)(luts2 + (obase + p) * NLUT) + q);
        float4 b = __ldg((const float4*)(luts2 + (obase + NPAIR + p) * NLUT) + q);
        unsigned long long* d = s_l2p + p * L2PS + q * 4;
        d[0] = pk2(a.x, b.x);
        d[1] = pk2(a.y - a.x, b.y - b.x);
        d[2] = pk2(a.z, b.z);
        d[3] = pk2(a.w - a.z, b.w - b.z);
    }
    for (int i = tid; i < B_OUT * 6; i += BTHREADS)
        s_idx[i] = __ldg(idx2 + obase * 6 + i);
    __syncthreads();

    if (tid < RG * NPAIR) {                  // 400 compute threads
        const int p = tid >> 3;
        const int r = tid & 7;
        const unsigned long long* Lp = s_l2p + p * L2PS;
        const float* h1g = g_h1 + (size_t)g * O1 * RG + r;
        const int* ipA = s_idx + p * 6;
        const int* ipB = s_idx + (p + NPAIR) * 6;

        unsigned long long xp5, xp4, xn4, xp3, xn3, xp2, xn2;
        {
            float a, b;
            a = __ldg(h1g + ipA[5] * RG); b = __ldg(h1g + ipB[5] * RG);
            xp5 = pk2(a, b);
            a = __ldg(h1g + ipA[4] * RG); b = __ldg(h1g + ipB[4] * RG);
            xp4 = pk2(a, b); xn4 = pk2(-a, -b);
            a = __ldg(h1g + ipA[3] * RG); b = __ldg(h1g + ipB[3] * RG);
            xp3 = pk2(a, b); xn3 = pk2(-a, -b);
            a = __ldg(h1g + ipA[2] * RG); b = __ldg(h1g + ipB[2] * RG);
            xp2 = pk2(a, b); xn2 = pk2(-a, -b);
        }

        unsigned long long u[4];
        #pragma unroll
        for (int t = 0; t < 4; t++) {
            const unsigned long long* Lt = Lp + 16 * t;
            ulonglong2 c;
            unsigned long long w0, w1, v0, v1, h0, h1v;
            c = *(const ulonglong2*)(Lt + 0);  w0 = fma2(xp5, c.y, c.x);
            c = *(const ulonglong2*)(Lt + 2);  w1 = fma2(xp5, c.y, c.x);
            v0 = lerp2(w0, w1, xp4, xn4);
            c = *(const ulonglong2*)(Lt + 4);  w0 = fma2(xp5, c.y, c.x);
            c = *(const ulonglong2*)(Lt + 6);  w1 = fma2(xp5, c.y, c.x);
            v1 = lerp2(w0, w1, xp4, xn4);
            h0 = lerp2(v0, v1, xp3, xn3);
            c = *(const ulonglong2*)(Lt + 8);  w0 = fma2(xp5, c.y, c.x);
            c = *(const ulonglong2*)(Lt + 10); w1 = fma2(xp5, c.y, c.x);
            v0 = lerp2(w0, w1, xp4, xn4);
            c = *(const ulonglong2*)(Lt + 12); w0 = fma2(xp5, c.y, c.x);
            c = *(const ulonglong2*)(Lt + 14); w1 = fma2(xp5, c.y, c.x);
            v1 = lerp2(w0, w1, xp4, xn4);
            h1v = lerp2(v0, v1, xp3, xn3);
            u[t] = lerp2(h0, h1v, xp2, xn2);
        }
        float a1, b1;
        a1 = __ldg(h1g + ipA[1] * RG); b1 = __ldg(h1g + ipB[1] * RG);
        unsigned long long xp1 = pk2(a1, b1), xn1 = pk2(-a1, -b1);
        unsigned long long t0 = lerp2(u[0], u[1], xp1, xn1);
        unsigned long long t1 = lerp2(u[2], u[3], xp1, xn1);
        a1 = __ldg(h1g + ipA[0] * RG); b1 = __ldg(h1g + ipB[0] * RG);
        unsigned long long xp0 = pk2(a1, b1), xn0 = pk2(-a1, -b1);
        unsigned long long res = lerp2(t0, t1, xp0, xn0);

        float hA, hB;
        upk2(hA, hB, res);
        s_h2[p * RG + r]           = hA;
        s_h2[(p + NPAIR) * RG + r] = hB;
    }
    __syncthreads();

    if (tid < RG) {
        const float* hp = s_h2 + tid;
        float s0 = 0.f, s1 = 0.f;
        #pragma unroll 4
        for (int j = 0; j < B_OUT; j += 2) {
            s0 += hp[(j + 0) * RG];
            s1 += hp[(j + 1) * RG];
        }
        out[(g * RG + tid) * NCLS + os] = (s0 + s1) / TAU;
    }
}

// ================== launch ==================
extern "C" void kernel_launch(void* const* d_in, const int* in_sizes, int n_in,
                              void* d_out, int out_size)
{
    const float* x      = (const float*)d_in[0];
    const float* thr    = (const float*)d_in[1];
    const float* luts1  = (const float*)d_in[2];
    const int*   idx1   = (const int*)  d_in[3];
    const float* luts2  = (const float*)d_in[4];
    const int*   idx2   = (const int*)  d_in[5];
    float*       out    = (float*)d_out;

    const int smemB = NPAIR * L2PS * 8 + B_OUT * 6 * 4 + B_OUT * RG * 4;
    static bool attr_set = false;
    if (!attr_set) {
        cudaFuncSetAttribute(kB_layer2, cudaFuncAttributeMaxDynamicSharedMemorySize, smemB);
        attr_set = true;
    }

    k01_layer1<<<NG * A_OSPL, 512>>>(x, thr, luts1, idx1);
    kB_layer2<<<NG * B_OSPL, BTHREADS, smemB>>>(luts2, idx2, out);
}